// round 13
// baseline (speedup 1.0000x reference)
#include <cuda_runtime.h>
#include <cuda_fp16.h>
#include <cstdint>

// ---------------------------------------------------------------------------
// x[4096,8192] fp32, qweight[1024,8192] i32 (4-bit packed along k),
// qzeros[64,1024] i32, scales[64,8192] fp32, bias[8192] fp32
//   -> out[4096,8192] fp32.
// Two-pass: merged prep kernel writes pre-swizzled fp16 tiles (exact-fp16
// dequant); gemm = PERSISTENT CTAs (1/SM), each walking multiple 128x256
// tiles with one seamless cross-tile k-chunk cp.async stream: next tile's
// loads are in flight during this tile's last superstages + epilogue.
// mma.sync.m16n8k16 fp16->fp32 (tcgen05 rejected by compute_103 virt arch).
// ---------------------------------------------------------------------------
#define TOKENS   4096
#define INF      8192
#define OUTF     8192
#define KCHUNK   64
#define KCHUNKS  128            // INF / KCHUNK
#define NSUPER   64             // KCHUNKS / 2
#define MT       32             // TOKENS / 128
#define NT       32             // OUTF / 256
#define NTILES   (MT * NT)      // 1024
#define A_TILE   16384          // 128 m-rows * 128B (64 fp16, K-major, SW128)
#define B_TILE   32768          // 256 n-rows * 128B
#define STAGE_BYTES (A_TILE + B_TILE)
#define NSTAGES  4
#define SMEM_DYN (NSTAGES * STAGE_BYTES + 1024)   // + align pad

// scratch: tile-major, pre-swizzled fp16 operands (device globals, no alloc)
__device__ __align__(1024) unsigned char g_xt[(size_t)MT * KCHUNKS * A_TILE]; // 64 MB
__device__ __align__(1024) unsigned char g_wt[(size_t)NT * KCHUNKS * B_TILE]; // 128 MB

// ---------------------------------------------------------------------------
// helpers
// ---------------------------------------------------------------------------
__device__ __forceinline__ uint32_t smem_to_u32(const void* p) {
    uint32_t a;
    asm("{ .reg .u64 t; cvta.to.shared.u64 t, %1; cvt.u32.u64 %0, t; }" : "=r"(a) : "l"(p));
    return a;
}

#define SWZ(o) ((o) ^ (((o) >> 3) & 0x70))

__device__ __forceinline__ void cp_async16(uint32_t dst, const void* src) {
    asm volatile("cp.async.cg.shared.global [%0], [%1], 16;" :: "r"(dst), "l"(src));
}
#define CP_COMMIT() asm volatile("cp.async.commit_group;" ::: "memory")
#define CP_WAIT(n)  asm volatile("cp.async.wait_group %0;" :: "n"(n) : "memory")

__device__ __forceinline__ void ldsm4(uint32_t& r0, uint32_t& r1, uint32_t& r2, uint32_t& r3,
                                      uint32_t addr) {
    asm volatile("ldmatrix.sync.aligned.m8n8.x4.shared.b16 {%0,%1,%2,%3}, [%4];"
        : "=r"(r0), "=r"(r1), "=r"(r2), "=r"(r3) : "r"(addr));
}

__device__ __forceinline__ void mma16816(float* c,
    uint32_t a0, uint32_t a1, uint32_t a2, uint32_t a3, uint32_t b0, uint32_t b1) {
    asm volatile("mma.sync.aligned.m16n8k16.row.col.f32.f16.f16.f32 "
        "{%0,%1,%2,%3}, {%4,%5,%6,%7}, {%8,%9}, {%0,%1,%2,%3};"
        : "+f"(c[0]), "+f"(c[1]), "+f"(c[2]), "+f"(c[3])
        : "r"(a0), "r"(a1), "r"(a2), "r"(a3), "r"(b0), "r"(b1));
}

union HU { unsigned u; __half2 h; };
__device__ __forceinline__ unsigned h2u(__half2 h) { HU t; t.h = h; return t.u; }
__device__ __forceinline__ __half2 u2h(unsigned u) { HU t; t.u = u; return t.h; }

// ---------------------------------------------------------------------------
// merged prep: blocks [0, 4096) convert x; blocks [4096, 8192) dequant W.
// Both write tile-major SW128 fp16 with k-octet permutation (k0,k4)(k1,k5)...
// W path: one thread per (n, 64k-chunk) -> 8 octet rows; zero/scale loaded
// once per 8 packed int32. Same per-element math/order -> bit-identical.
// grid 8192 x 256 threads
// ---------------------------------------------------------------------------
__global__ void __launch_bounds__(256) prep_kernel(
    const float* __restrict__ x,
    const int* __restrict__ qw, const int* __restrict__ qz,
    const float* __restrict__ sc)
{
    int b = blockIdx.x;
    if (b < 4096) {
        // ---- x: fp32 -> fp16, tile (mt, kc) ----
        int mt = b >> 7;                // 0..31
        int kc = b & 127;               // 0..127
        unsigned char* tile = g_xt + ((size_t)(mt * KCHUNKS + kc)) * A_TILE;
        const float* xrowbase = x + (size_t)mt * 128 * INF + (size_t)kc * KCHUNK;
        for (int u = threadIdx.x; u < 1024; u += 256) {   // 128 rows * 8 octets
            int row = u >> 3, oct = u & 7;
            const float4* p = (const float4*)(xrowbase + (size_t)row * INF + oct * 8);
            float4 a = p[0];
            float4 bb = p[1];
            uint4 o;
            o.x = h2u(__floats2half2_rn(a.x, bb.x));   // (k0, k4)
            o.y = h2u(__floats2half2_rn(a.y, bb.y));   // (k1, k5)
            o.z = h2u(__floats2half2_rn(a.z, bb.z));   // (k2, k6)
            o.w = h2u(__floats2half2_rn(a.w, bb.w));   // (k3, k7)
            *(uint4*)(tile + SWZ(row * 128 + oct * 16)) = o;
        }
    } else {
        // ---- W: int4 unpack + dequant -> fp16 (exact (1024+w)-(1024+z+1)) ----
        int b2 = b - 4096;              // 0..4095
        int kc = b2 & 127;              // 64-k chunk index
        int n  = (b2 >> 7) * 256 + threadIdx.x;   // 0..8191
        int g  = kc >> 1;               // 128-k quant group

        unsigned zq = (unsigned)qz[(size_t)g * (OUTF / 8) + (n >> 3)];
        unsigned z  = (zq >> ((n & 7) * 4)) & 0xF;
        unsigned zb = 0x6400u + z + 1u;        // fp16 bits of (1024+z+1), exact
        __half2 zh2 = u2h(zb | (zb << 16));
        __half2 sh2 = __float2half2_rn(sc[(size_t)g * OUTF + n]);

        int rr = n & 255;               // n-row within 256-wide tile
        unsigned char* tile = g_wt + ((size_t)((n >> 8) * KCHUNKS + kc)) * B_TILE;
        const int* qrow = qw + (size_t)(kc * 8) * OUTF + n;
        const unsigned m = 0x000F000Fu, add = 0x64006400u;
        #pragma unroll
        for (int oct = 0; oct < 8; oct++) {
            unsigned q = (unsigned)qrow[(size_t)oct * OUTF];
            unsigned v0 = (q & m) | add;           // (1024+k0, 1024+k4)
            unsigned v1 = ((q >> 4) & m) | add;    // (k1, k5)
            unsigned v2 = ((q >> 8) & m) | add;    // (k2, k6)
            unsigned v3 = ((q >> 12) & m) | add;   // (k3, k7)
            uint4 o;
            o.x = h2u(__hmul2(__hsub2(u2h(v0), zh2), sh2));
            o.y = h2u(__hmul2(__hsub2(u2h(v1), zh2), sh2));
            o.z = h2u(__hmul2(__hsub2(u2h(v2), zh2), sh2));
            o.w = h2u(__hmul2(__hsub2(u2h(v3), zh2), sh2));
            *(uint4*)(tile + SWZ(rr * 128 + oct * 16)) = o;
        }
    }
}

// ---------------------------------------------------------------------------
// persistent gemm: grid = #SMs, 1 CTA/SM. Each CTA processes tiles
// bid, bid+grid, ... Tile = 128M x 256N, 8 warps (2x4) of 64x64.
// One continuous superstage stream (2 chunks / iter) across ALL of a CTA's
// tiles: slot ping-pong (2s)&3 is coherent (128 chunks/tile % 4 == 0), so
// next tile's loads fly during this tile's last superstages + epilogue.
// ---------------------------------------------------------------------------
__global__ void __launch_bounds__(256, 1) gemm_kernel(
    const float* __restrict__ bias, float* __restrict__ out)
{
    extern __shared__ unsigned char smem_raw[];
    uint32_t base = (smem_to_u32(smem_raw) + 1023u) & ~1023u;

    int tid = threadIdx.x, wid = tid >> 5, lane = tid & 31;
    int wm = wid >> 2, wn = wid & 3;           // warp grid 2(m) x 4(n)
    int bid = blockIdx.x, grid = gridDim.x;

    int ntiles = (NTILES - bid + grid - 1) / grid;   // tiles for this CTA (>=0)
    int S = ntiles * NSUPER;                         // total superstages

    // fill both chunk slots of superstage s (cross-tile source resolution)
    auto load_ss = [&](int s) {
        int ti = bid + (s >> 6) * grid;              // tile id (NSUPER==64)
        const unsigned char* gA = g_xt + (size_t)(ti & 31) * KCHUNKS * A_TILE;
        const unsigned char* gB = g_wt + (size_t)(ti >> 5) * KCHUNKS * B_TILE;
        int c0 = (s & 63) * 2;                       // chunk within tile
        #pragma unroll
        for (int h = 0; h < 2; h++) {
            int c = c0 + h;
            uint32_t sd = base + (uint32_t)(c & 3) * STAGE_BYTES;
            const unsigned char* aS = gA + (size_t)c * A_TILE;
            const unsigned char* bS = gB + (size_t)c * B_TILE;
            #pragma unroll
            for (int i = 0; i < 4; i++)
                cp_async16(sd + (tid + 256 * i) * 16, aS + (size_t)(tid + 256 * i) * 16);
            #pragma unroll
            for (int i = 0; i < 8; i++)
                cp_async16(sd + A_TILE + (tid + 256 * i) * 16, bS + (size_t)(tid + 256 * i) * 16);
        }
        CP_COMMIT();
    };

    // ldmatrix per-lane geometry (validated rounds 3/6/7/8/9/10/12).
    int gq = lane >> 3, r = lane & 7;
    int aRow0 = wm * 64 + (gq & 1) * 8 + r;   int aGh = gq >> 1;
    int bRow0 = wn * 64 + (gq >> 1) * 8 + r;  int bGl = gq & 1;

    float acc[4][8][4];
    #pragma unroll
    for (int i = 0; i < 4; i++)
        #pragma unroll
        for (int j = 0; j < 8; j++)
            #pragma unroll
            for (int k = 0; k < 4; k++) acc[i][j][k] = 0.f;

    // double-buffered fragments (all indices compile-time)
    uint32_t afr[2][4][4], bfr[2][4][4];

#define PREFETCH(BUF, BASE, C) do {                                               \
        uint32_t _sA = (BASE), _sB = (BASE) + A_TILE;                             \
        _Pragma("unroll")                                                         \
        for (int mb = 0; mb < 4; mb++) {                                          \
            uint32_t off = (uint32_t)(aRow0 + mb * 16) * 128u                     \
                         + (uint32_t)(((2 * (C) + aGh) ^ r) << 4);                \
            ldsm4(afr[BUF][mb][0], afr[BUF][mb][1], afr[BUF][mb][2],              \
                  afr[BUF][mb][3], _sA + off);                                    \
        }                                                                         \
        _Pragma("unroll")                                                         \
        for (int p = 0; p < 4; p++) {                                             \
            uint32_t off = (uint32_t)(bRow0 + p * 16) * 128u                      \
                         + (uint32_t)(((2 * (C) + bGl) ^ r) << 4);                \
            ldsm4(bfr[BUF][p][0], bfr[BUF][p][1], bfr[BUF][p][2],                 \
                  bfr[BUF][p][3], _sB + off);                                     \
        }                                                                         \
    } while (0)

#define MMASTEP(BUF) do {                                                         \
        _Pragma("unroll")                                                         \
        for (int mb = 0; mb < 4; mb++)                                            \
            _Pragma("unroll")                                                     \
            for (int p = 0; p < 4; p++) {                                         \
                mma16816(acc[mb][2 * p],     afr[BUF][mb][0], afr[BUF][mb][1],    \
                         afr[BUF][mb][2], afr[BUF][mb][3],                        \
                         bfr[BUF][p][0], bfr[BUF][p][1]);                         \
                mma16816(acc[mb][2 * p + 1], afr[BUF][mb][0], afr[BUF][mb][1],    \
                         afr[BUF][mb][2], afr[BUF][mb][3],                        \
                         bfr[BUF][p][2], bfr[BUF][p][3]);                         \
            }                                                                     \
    } while (0)

    if (S > 0) {
        // prologue: superstages 0 and 1 of the stream in flight
        load_ss(0);
        if (S > 1) load_ss(1);
        CP_WAIT(1);            // superstage 0 complete (if S==1, waits all)
        __syncthreads();       // ...and visible
        PREFETCH(0, base, 0);  // stream chunk 0, step 0
    }

    #pragma unroll 1
    for (int s = 0; s < S; s++) {
        uint32_t cb0 = base + (uint32_t)((2 * s) & 3) * STAGE_BYTES;   // chunk 2s
        uint32_t cb1 = cb0 + STAGE_BYTES;                              // chunk 2s+1

        PREFETCH(1, cb0, 1); MMASTEP(0);
        PREFETCH(0, cb0, 2); MMASTEP(1);
        PREFETCH(1, cb0, 3); MMASTEP(0);
        PREFETCH(0, cb1, 0); MMASTEP(1);
        PREFETCH(1, cb1, 1); MMASTEP(0);
        PREFETCH(0, cb1, 2); MMASTEP(1);
        PREFETCH(1, cb1, 3); MMASTEP(0);
        MMASTEP(1);

        if ((s & (NSUPER - 1)) == NSUPER - 1) {
            // epilogue for the tile just finished (overlaps in-flight loads
            // of the NEXT tile committed at s-1). Registers+gmem only.
            int ti = bid + (s >> 6) * grid;
            int mt = ti & 31, nt = ti >> 5;
            int rowBase = mt * 128 + wm * 64 + (lane >> 2);
            int colBase = nt * 256 + wn * 64 + 2 * (lane & 3);
            #pragma unroll
            for (int nb = 0; nb < 8; nb++) {
                int n0 = colBase + nb * 8;
                float2 bv = *(const float2*)(bias + n0);
                #pragma unroll
                for (int mb = 0; mb < 4; mb++) {
                    int m0 = rowBase + mb * 16;
                    float2 v0 = { acc[mb][nb][0] + bv.x, acc[mb][nb][1] + bv.y };
                    float2 v1 = { acc[mb][nb][2] + bv.x, acc[mb][nb][3] + bv.y };
                    *(float2*)(out + (size_t)m0 * OUTF + n0) = v0;
                    *(float2*)(out + (size_t)(m0 + 8) * OUTF + n0) = v1;
                }
            }
            #pragma unroll
            for (int i = 0; i < 4; i++)
                #pragma unroll
                for (int j = 0; j < 8; j++)
                    #pragma unroll
                    for (int k = 0; k < 4; k++) acc[i][j][k] = 0.f;
        }

        CP_WAIT(0);        // superstage s+1 (committed at s-1) resident
        __syncthreads();   // all reads of slots (2s)&3,(2s+1)&3 done; publish
        if (s + 2 < S) load_ss(s + 2);       // refill just-consumed slots
        if (s + 1 < S)                       // first fragment of next superstage
            PREFETCH(0, base + (uint32_t)((2 * s + 2) & 3) * STAGE_BYTES, 0);
    }

#undef PREFETCH
#undef MMASTEP
}

// ---------------------------------------------------------------------------
// launch
// ---------------------------------------------------------------------------
extern "C" void kernel_launch(void* const* d_in, const int* in_sizes, int n_in,
                              void* d_out, int out_size) {
    const float* x      = (const float*)d_in[0];
    const int*   qw     = (const int*)d_in[1];
    const int*   qz     = (const int*)d_in[2];
    const float* scales = (const float*)d_in[3];
    const float* bias   = (const float*)d_in[4];
    float* out = (float*)d_out;

    static int grid_sm = 0;
    if (!grid_sm) {
        cudaFuncSetAttribute(gemm_kernel, cudaFuncAttributeMaxDynamicSharedMemorySize, SMEM_DYN);
        int sms = 0;
        cudaDeviceGetAttribute(&sms, cudaDevAttrMultiProcessorCount, 0);
        grid_sm = (sms > 0 && sms <= NTILES) ? sms : 148;
    }

    prep_kernel<<<8192, 256>>>(x, qw, qz, scales);

    gemm_kernel<<<grid_sm, 256, SMEM_DYN>>>(bias, out);
}

// round 14
// speedup vs baseline: 1.2800x; 1.2800x over previous
#include <cuda_runtime.h>
#include <cuda_fp16.h>
#include <cstdint>

// ---------------------------------------------------------------------------
// x[4096,8192] fp32, qweight[1024,8192] i32 (4-bit packed along k),
// qzeros[64,1024] i32, scales[64,8192] fp32, bias[8192] fp32
//   -> out[4096,8192] fp32.
// Two-pass: merged prep kernel writes pre-swizzled fp16 tiles (exact-fp16
// dequant); gemm = PERSISTENT CTAs (1/SM) v2: nested loops (outer tile,
// inner superstage) so the hot loop is byte-identical to the round-12
// champion; tile pointers resolved once per tile; epilogue hoisted out of
// the inner loop. Cross-tile chunk stream keeps cp.async slots coherent
// (128 chunks/tile % 4 == 0). mma.sync.m16n8k16 fp16->fp32.
// ---------------------------------------------------------------------------
#define TOKENS   4096
#define INF      8192
#define OUTF     8192
#define KCHUNK   64
#define KCHUNKS  128            // INF / KCHUNK
#define NSUPER   64             // KCHUNKS / 2
#define MT       32             // TOKENS / 128
#define NT       32             // OUTF / 256
#define NTILES   (MT * NT)      // 1024
#define A_TILE   16384          // 128 m-rows * 128B (64 fp16, K-major, SW128)
#define B_TILE   32768          // 256 n-rows * 128B
#define STAGE_BYTES (A_TILE + B_TILE)
#define NSTAGES  4
#define SMEM_DYN (NSTAGES * STAGE_BYTES + 1024)   // + align pad

// scratch: tile-major, pre-swizzled fp16 operands (device globals, no alloc)
__device__ __align__(1024) unsigned char g_xt[(size_t)MT * KCHUNKS * A_TILE]; // 64 MB
__device__ __align__(1024) unsigned char g_wt[(size_t)NT * KCHUNKS * B_TILE]; // 128 MB

// ---------------------------------------------------------------------------
// helpers
// ---------------------------------------------------------------------------
__device__ __forceinline__ uint32_t smem_to_u32(const void* p) {
    uint32_t a;
    asm("{ .reg .u64 t; cvta.to.shared.u64 t, %1; cvt.u32.u64 %0, t; }" : "=r"(a) : "l"(p));
    return a;
}

#define SWZ(o) ((o) ^ (((o) >> 3) & 0x70))

__device__ __forceinline__ void cp_async16(uint32_t dst, const void* src) {
    asm volatile("cp.async.cg.shared.global [%0], [%1], 16;" :: "r"(dst), "l"(src));
}
#define CP_COMMIT() asm volatile("cp.async.commit_group;" ::: "memory")
#define CP_WAIT(n)  asm volatile("cp.async.wait_group %0;" :: "n"(n) : "memory")

__device__ __forceinline__ void ldsm4(uint32_t& r0, uint32_t& r1, uint32_t& r2, uint32_t& r3,
                                      uint32_t addr) {
    asm volatile("ldmatrix.sync.aligned.m8n8.x4.shared.b16 {%0,%1,%2,%3}, [%4];"
        : "=r"(r0), "=r"(r1), "=r"(r2), "=r"(r3) : "r"(addr));
}

__device__ __forceinline__ void mma16816(float* c,
    uint32_t a0, uint32_t a1, uint32_t a2, uint32_t a3, uint32_t b0, uint32_t b1) {
    asm volatile("mma.sync.aligned.m16n8k16.row.col.f32.f16.f16.f32 "
        "{%0,%1,%2,%3}, {%4,%5,%6,%7}, {%8,%9}, {%0,%1,%2,%3};"
        : "+f"(c[0]), "+f"(c[1]), "+f"(c[2]), "+f"(c[3])
        : "r"(a0), "r"(a1), "r"(a2), "r"(a3), "r"(b0), "r"(b1));
}

union HU { unsigned u; __half2 h; };
__device__ __forceinline__ unsigned h2u(__half2 h) { HU t; t.h = h; return t.u; }
__device__ __forceinline__ __half2 u2h(unsigned u) { HU t; t.u = u; return t.h; }

// ---------------------------------------------------------------------------
// merged prep: blocks [0, 4096) convert x; blocks [4096, 8192) dequant W.
// Both write tile-major SW128 fp16 with k-octet permutation (k0,k4)(k1,k5)...
// W path: one thread per (n, 64k-chunk) -> 8 octet rows; zero/scale loaded
// once per 8 packed int32. Same per-element math/order -> bit-identical.
// grid 8192 x 256 threads
// ---------------------------------------------------------------------------
__global__ void __launch_bounds__(256) prep_kernel(
    const float* __restrict__ x,
    const int* __restrict__ qw, const int* __restrict__ qz,
    const float* __restrict__ sc)
{
    int b = blockIdx.x;
    if (b < 4096) {
        // ---- x: fp32 -> fp16, tile (mt, kc) ----
        int mt = b >> 7;                // 0..31
        int kc = b & 127;               // 0..127
        unsigned char* tile = g_xt + ((size_t)(mt * KCHUNKS + kc)) * A_TILE;
        const float* xrowbase = x + (size_t)mt * 128 * INF + (size_t)kc * KCHUNK;
        for (int u = threadIdx.x; u < 1024; u += 256) {   // 128 rows * 8 octets
            int row = u >> 3, oct = u & 7;
            const float4* p = (const float4*)(xrowbase + (size_t)row * INF + oct * 8);
            float4 a = p[0];
            float4 bb = p[1];
            uint4 o;
            o.x = h2u(__floats2half2_rn(a.x, bb.x));   // (k0, k4)
            o.y = h2u(__floats2half2_rn(a.y, bb.y));   // (k1, k5)
            o.z = h2u(__floats2half2_rn(a.z, bb.z));   // (k2, k6)
            o.w = h2u(__floats2half2_rn(a.w, bb.w));   // (k3, k7)
            *(uint4*)(tile + SWZ(row * 128 + oct * 16)) = o;
        }
    } else {
        // ---- W: int4 unpack + dequant -> fp16 (exact (1024+w)-(1024+z+1)) ----
        int b2 = b - 4096;              // 0..4095
        int kc = b2 & 127;              // 64-k chunk index
        int n  = (b2 >> 7) * 256 + threadIdx.x;   // 0..8191
        int g  = kc >> 1;               // 128-k quant group

        unsigned zq = (unsigned)qz[(size_t)g * (OUTF / 8) + (n >> 3)];
        unsigned z  = (zq >> ((n & 7) * 4)) & 0xF;
        unsigned zb = 0x6400u + z + 1u;        // fp16 bits of (1024+z+1), exact
        __half2 zh2 = u2h(zb | (zb << 16));
        __half2 sh2 = __float2half2_rn(sc[(size_t)g * OUTF + n]);

        int rr = n & 255;               // n-row within 256-wide tile
        unsigned char* tile = g_wt + ((size_t)((n >> 8) * KCHUNKS + kc)) * B_TILE;
        const int* qrow = qw + (size_t)(kc * 8) * OUTF + n;
        const unsigned m = 0x000F000Fu, add = 0x64006400u;
        #pragma unroll
        for (int oct = 0; oct < 8; oct++) {
            unsigned q = (unsigned)qrow[(size_t)oct * OUTF];
            unsigned v0 = (q & m) | add;           // (1024+k0, 1024+k4)
            unsigned v1 = ((q >> 4) & m) | add;    // (k1, k5)
            unsigned v2 = ((q >> 8) & m) | add;    // (k2, k6)
            unsigned v3 = ((q >> 12) & m) | add;   // (k3, k7)
            uint4 o;
            o.x = h2u(__hmul2(__hsub2(u2h(v0), zh2), sh2));
            o.y = h2u(__hmul2(__hsub2(u2h(v1), zh2), sh2));
            o.z = h2u(__hmul2(__hsub2(u2h(v2), zh2), sh2));
            o.w = h2u(__hmul2(__hsub2(u2h(v3), zh2), sh2));
            *(uint4*)(tile + SWZ(rr * 128 + oct * 16)) = o;
        }
    }
}

// ---------------------------------------------------------------------------
// persistent gemm v2: grid = #SMs, tiles bid, bid+grid, ...  Nested loops:
// outer resolves tile pointers ONCE (cur + next); inner superstage loop is
// the round-12 champion body. Tail of inner loop loads cur ss s+2, except
// s=62/63 which load next tile ss 0/1. Epilogue hoisted after the inner
// loop (overlaps next tile's in-flight ss1 load; next ss0 already resident
// and its first fragment prefetched).
// ---------------------------------------------------------------------------
__global__ void __launch_bounds__(256, 1) gemm_kernel(
    const float* __restrict__ bias, float* __restrict__ out)
{
    extern __shared__ unsigned char smem_raw[];
    uint32_t base = (smem_to_u32(smem_raw) + 1023u) & ~1023u;

    int tid = threadIdx.x, wid = tid >> 5, lane = tid & 31;
    int wm = wid >> 2, wn = wid & 3;           // warp grid 2(m) x 4(n)
    int bid = blockIdx.x, grid = gridDim.x;

    // load one superstage (2 chunks) from explicit tile pointers; 1 commit
    auto load_ss = [&](const unsigned char* gA, const unsigned char* gB, int ss) {
        int c0 = ss * 2;
        #pragma unroll
        for (int h = 0; h < 2; h++) {
            int c = c0 + h;
            uint32_t sd = base + (uint32_t)(c & 3) * STAGE_BYTES;
            const unsigned char* aS = gA + (size_t)c * A_TILE;
            const unsigned char* bS = gB + (size_t)c * B_TILE;
            #pragma unroll
            for (int i = 0; i < 4; i++)
                cp_async16(sd + (tid + 256 * i) * 16, aS + (size_t)(tid + 256 * i) * 16);
            #pragma unroll
            for (int i = 0; i < 8; i++)
                cp_async16(sd + A_TILE + (tid + 256 * i) * 16, bS + (size_t)(tid + 256 * i) * 16);
        }
        CP_COMMIT();
    };

    // ldmatrix per-lane geometry (validated rounds 3/6/7/8/9/10/12/13).
    int gq = lane >> 3, r = lane & 7;
    int aRow0 = wm * 64 + (gq & 1) * 8 + r;   int aGh = gq >> 1;
    int bRow0 = wn * 64 + (gq >> 1) * 8 + r;  int bGl = gq & 1;

    float acc[4][8][4];
    #pragma unroll
    for (int i = 0; i < 4; i++)
        #pragma unroll
        for (int j = 0; j < 8; j++)
            #pragma unroll
            for (int k = 0; k < 4; k++) acc[i][j][k] = 0.f;

    // double-buffered fragments (all indices compile-time)
    uint32_t afr[2][4][4], bfr[2][4][4];

#define PREFETCH(BUF, BASE, C) do {                                               \
        uint32_t _sA = (BASE), _sB = (BASE) + A_TILE;                             \
        _Pragma("unroll")                                                         \
        for (int mb = 0; mb < 4; mb++) {                                          \
            uint32_t off = (uint32_t)(aRow0 + mb * 16) * 128u                     \
                         + (uint32_t)(((2 * (C) + aGh) ^ r) << 4);                \
            ldsm4(afr[BUF][mb][0], afr[BUF][mb][1], afr[BUF][mb][2],              \
                  afr[BUF][mb][3], _sA + off);                                    \
        }                                                                         \
        _Pragma("unroll")                                                         \
        for (int p = 0; p < 4; p++) {                                             \
            uint32_t off = (uint32_t)(bRow0 + p * 16) * 128u                      \
                         + (uint32_t)(((2 * (C) + bGl) ^ r) << 4);                \
            ldsm4(bfr[BUF][p][0], bfr[BUF][p][1], bfr[BUF][p][2],                 \
                  bfr[BUF][p][3], _sB + off);                                     \
        }                                                                         \
    } while (0)

#define MMASTEP(BUF) do {                                                         \
        _Pragma("unroll")                                                         \
        for (int mb = 0; mb < 4; mb++)                                            \
            _Pragma("unroll")                                                     \
            for (int p = 0; p < 4; p++) {                                         \
                mma16816(acc[mb][2 * p],     afr[BUF][mb][0], afr[BUF][mb][1],    \
                         afr[BUF][mb][2], afr[BUF][mb][3],                        \
                         bfr[BUF][p][0], bfr[BUF][p][1]);                         \
                mma16816(acc[mb][2 * p + 1], afr[BUF][mb][0], afr[BUF][mb][1],    \
                         afr[BUF][mb][2], afr[BUF][mb][3],                        \
                         bfr[BUF][p][2], bfr[BUF][p][3]);                         \
            }                                                                     \
    } while (0)

    if (bid < NTILES) {
        // prologue: superstages 0,1 of first tile in flight
        {
            const unsigned char* gA0 = g_xt + (size_t)(bid & 31) * KCHUNKS * A_TILE;
            const unsigned char* gB0 = g_wt + (size_t)(bid >> 5) * KCHUNKS * B_TILE;
            load_ss(gA0, gB0, 0);
            load_ss(gA0, gB0, 1);
        }
        CP_WAIT(1);            // superstage 0 complete
        __syncthreads();       // ...and visible
        PREFETCH(0, base, 0);  // chunk 0, step 0

        #pragma unroll 1
        for (int ti = bid; ti < NTILES; ti += grid) {
            int mt = ti & 31, nt = ti >> 5;
            const unsigned char* gA = g_xt + (size_t)mt * KCHUNKS * A_TILE;
            const unsigned char* gB = g_wt + (size_t)nt * KCHUNKS * B_TILE;
            int tn = ti + grid;
            bool has_next = tn < NTILES;
            const unsigned char* gA2 = g_xt + (size_t)(tn & 31) * KCHUNKS * A_TILE;
            const unsigned char* gB2 = g_wt + (size_t)(tn >> 5) * KCHUNKS * B_TILE;

            #pragma unroll 1
            for (int s = 0; s < NSUPER; s++) {
                uint32_t cb0 = base + (uint32_t)((2 * s) & 3) * STAGE_BYTES;
                uint32_t cb1 = cb0 + STAGE_BYTES;

                PREFETCH(1, cb0, 1); MMASTEP(0);
                PREFETCH(0, cb0, 2); MMASTEP(1);
                PREFETCH(1, cb0, 3); MMASTEP(0);
                PREFETCH(0, cb1, 0); MMASTEP(1);
                PREFETCH(1, cb1, 1); MMASTEP(0);
                PREFETCH(0, cb1, 2); MMASTEP(1);
                PREFETCH(1, cb1, 3); MMASTEP(0);
                MMASTEP(1);

                CP_WAIT(0);        // superstage s+1 of stream resident
                __syncthreads();   // slots of ss s free in all threads
                if (s < NSUPER - 2)      load_ss(gA, gB, s + 2);
                else if (has_next)       load_ss(gA2, gB2, s - (NSUPER - 2));
                if (s < NSUPER - 1)
                    PREFETCH(0, base + (uint32_t)((2 * s + 2) & 3) * STAGE_BYTES, 0);
                else if (has_next)
                    PREFETCH(0, base, 0);   // next tile chunk 0, slot 0
            }

            // epilogue (registers + gmem only; overlaps next tile's loads)
            int rowBase = mt * 128 + wm * 64 + (lane >> 2);
            int colBase = nt * 256 + wn * 64 + 2 * (lane & 3);
            #pragma unroll
            for (int nb = 0; nb < 8; nb++) {
                int n0 = colBase + nb * 8;
                float2 bv = *(const float2*)(bias + n0);
                #pragma unroll
                for (int mb = 0; mb < 4; mb++) {
                    int m0 = rowBase + mb * 16;
                    float2 v0 = { acc[mb][nb][0] + bv.x, acc[mb][nb][1] + bv.y };
                    float2 v1 = { acc[mb][nb][2] + bv.x, acc[mb][nb][3] + bv.y };
                    *(float2*)(out + (size_t)m0 * OUTF + n0) = v0;
                    *(float2*)(out + (size_t)(m0 + 8) * OUTF + n0) = v1;
                }
            }
            #pragma unroll
            for (int i = 0; i < 4; i++)
                #pragma unroll
                for (int j = 0; j < 8; j++)
                    #pragma unroll
                    for (int k = 0; k < 4; k++) acc[i][j][k] = 0.f;
        }
    }

#undef PREFETCH
#undef MMASTEP
}

// ---------------------------------------------------------------------------
// launch
// ---------------------------------------------------------------------------
extern "C" void kernel_launch(void* const* d_in, const int* in_sizes, int n_in,
                              void* d_out, int out_size) {
    const float* x      = (const float*)d_in[0];
    const int*   qw     = (const int*)d_in[1];
    const int*   qz     = (const int*)d_in[2];
    const float* scales = (const float*)d_in[3];
    const float* bias   = (const float*)d_in[4];
    float* out = (float*)d_out;

    static int grid_sm = 0;
    if (!grid_sm) {
        cudaFuncSetAttribute(gemm_kernel, cudaFuncAttributeMaxDynamicSharedMemorySize, SMEM_DYN);
        int sms = 0;
        cudaDeviceGetAttribute(&sms, cudaDevAttrMultiProcessorCount, 0);
        grid_sm = (sms > 0 && sms <= NTILES) ? sms : 148;
    }

    prep_kernel<<<8192, 256>>>(x, qw, qz, scales);

    gemm_kernel<<<grid_sm, 256, SMEM_DYN>>>(bias, out);
}